// round 15
// baseline (speedup 1.0000x reference)
#include <cuda_runtime.h>
#include <cuda_bf16.h>

#define NN   50000
#define NNP  50176              // padded to multiple of 256
#define FIN  128
#define HID  256
#define NCLS 40
#define EE   600000
#define BN_EPS 1e-5f
#define NBLK 98                 // scan blocks: 98*512 = 50176 >= NN

// ---------------- device scratch (zero-initialized, no allocs) -----------
__device__ __nv_bfloat16 g_xhi[(size_t)NN * FIN];    // x split hi
__device__ __nv_bfloat16 g_xlo[(size_t)NN * FIN];    // x split lo
__device__ __nv_bfloat16 g_ahi[(size_t)NNP * FIN];   // hi(BN0-folded agg1)
__device__ __nv_bfloat16 g_alo[(size_t)NNP * FIN];   // lo residual
__device__ __nv_bfloat16 g_w1t_hi[HID * FIN];        // W1^T hi  [n][k]
__device__ __nv_bfloat16 g_w1t_lo[HID * FIN];        // W1^T lo
__device__ __nv_bfloat16 g_w2t_hi[48 * HID];         // W2^T hi [n][k], n pad 48
__device__ __nv_bfloat16 g_w2t_lo[48 * HID];         // W2^T lo
__device__ __nv_bfloat16 g_h1hi[(size_t)NNP * HID];  // h1 hi
__device__ __nv_bfloat16 g_h1lo[(size_t)NNP * HID];  // h1 lo
__device__ float g_s0[FIN], g_t0[FIN];               // BN0 affine
__device__ float g_s1[HID], g_d1[HID];               // BN1 scale, b1*s1+t1
__device__ int   g_deg[NN];
__device__ int   g_rowptr[NN + 1];
__device__ int   g_cursor[NN];
__device__ int   g_csr[EE];
__device__ int   g_bsum[NBLK];
__device__ float g_y[NN * NCLS];
__device__ int   g_idx64;

// ---------------- mma.sync / ldmatrix helpers (base ISA) ------------------
__device__ __forceinline__ unsigned smem_u32(const void* p) {
    unsigned a;
    asm("{ .reg .u64 t; cvta.to.shared.u64 t, %1; cvt.u32.u64 %0, t; }" : "=r"(a) : "l"(p));
    return a;
}
__device__ __forceinline__ void ldsm4(unsigned* r, unsigned addr) {
    asm volatile("ldmatrix.sync.aligned.m8n8.x4.shared.b16 {%0,%1,%2,%3}, [%4];"
                 : "=r"(r[0]), "=r"(r[1]), "=r"(r[2]), "=r"(r[3]) : "r"(addr));
}
__device__ __forceinline__ void mma_bf16(float* d, const unsigned* a, const unsigned* b) {
    asm volatile(
        "mma.sync.aligned.m16n8k16.row.col.f32.bf16.bf16.f32 "
        "{%0,%1,%2,%3}, {%4,%5,%6,%7}, {%8,%9}, {%0,%1,%2,%3};"
        : "+f"(d[0]), "+f"(d[1]), "+f"(d[2]), "+f"(d[3])
        : "r"(a[0]), "r"(a[1]), "r"(a[2]), "r"(a[3]), "r"(b[0]), "r"(b[1]));
}
__device__ __forceinline__ unsigned packbf2(float a, float b) {
    unsigned r;
    asm("cvt.rn.satfinite.bf16x2.f32 %0, %1, %2;" : "=r"(r) : "f"(b), "f"(a));
    return r;
}
// bf16x2 word -> two floats (low element, high element): pure bit shifts
__device__ __forceinline__ float bflo(unsigned u) { return __uint_as_float(u << 16); }
__device__ __forceinline__ float bfhi(unsigned u) { return __uint_as_float(u & 0xFFFF0000u); }

extern __shared__ char dyn_smem[];

// ---------------- init: detect + zero deg + BN affines + W/x splits -------
__global__ void init_kernel(const float* __restrict__ x,
                            const unsigned int* __restrict__ ei,
                            const float* __restrict__ bn0g, const float* __restrict__ bn0b,
                            const float* __restrict__ bn0m, const float* __restrict__ bn0v,
                            const float* __restrict__ W1, const float* __restrict__ b1,
                            const float* __restrict__ bn1g, const float* __restrict__ bn1b,
                            const float* __restrict__ bn1m, const float* __restrict__ bn1v,
                            const float* __restrict__ W2) {
    int t = blockIdx.x * blockDim.x + threadIdx.x;
    // ---- x -> bf16 hi/lo split (one float4 per thread) ----
    if (t < NN * (FIN / 4)) {
        float4 v = __ldg((const float4*)x + t);
        __nv_bfloat16 h0 = __float2bfloat16_rn(v.x), h1 = __float2bfloat16_rn(v.y);
        __nv_bfloat16 h2 = __float2bfloat16_rn(v.z), h3 = __float2bfloat16_rn(v.w);
        ushort4 hv, lv;
        hv.x = __bfloat16_as_ushort(h0); hv.y = __bfloat16_as_ushort(h1);
        hv.z = __bfloat16_as_ushort(h2); hv.w = __bfloat16_as_ushort(h3);
        lv.x = __bfloat16_as_ushort(__float2bfloat16_rn(v.x - __bfloat162float(h0)));
        lv.y = __bfloat16_as_ushort(__float2bfloat16_rn(v.y - __bfloat162float(h1)));
        lv.z = __bfloat16_as_ushort(__float2bfloat16_rn(v.z - __bfloat162float(h2)));
        lv.w = __bfloat16_as_ushort(__float2bfloat16_rn(v.w - __bfloat162float(h3)));
        ((ushort4*)g_xhi)[t] = hv;
        ((ushort4*)g_xlo)[t] = lv;
    }
    if (t < NN) g_deg[t] = 0;
    if (blockIdx.x == 0 && threadIdx.x < 32) {
        int l = threadIdx.x;
        unsigned any = 0;
        for (int k = l; k < 1024; k += 32) any |= ei[2 * k + 1];
#pragma unroll
        for (int off = 16; off > 0; off >>= 1) any |= __shfl_xor_sync(0xFFFFFFFFu, any, off);
        if (l == 0) g_idx64 = (any == 0) ? 1 : 0;
    }
    if (t < FIN) {
        float s0 = bn0g[t] * rsqrtf(bn0v[t] + BN_EPS);
        g_s0[t] = s0;
        g_t0[t] = bn0b[t] - bn0m[t] * s0;
    }
    if (t < HID) {
        float s1 = bn1g[t] * rsqrtf(bn1v[t] + BN_EPS);
        g_s1[t] = s1;
        g_d1[t] = b1[t] * s1 + (bn1b[t] - bn1m[t] * s1);
    }
    if (t < FIN * HID) {
        int k = t / HID;
        int n = t % HID;
        float w = W1[t];
        __nv_bfloat16 hi = __float2bfloat16_rn(w);
        __nv_bfloat16 lo = __float2bfloat16_rn(w - __bfloat162float(hi));
        g_w1t_hi[n * FIN + k] = hi;
        g_w1t_lo[n * FIN + k] = lo;
    }
    if (t < HID * NCLS) {
        int k = t / NCLS;
        int n = t % NCLS;
        float w = W2[t];
        __nv_bfloat16 hi = __float2bfloat16_rn(w);
        __nv_bfloat16 lo = __float2bfloat16_rn(w - __bfloat162float(hi));
        g_w2t_hi[n * HID + k] = hi;
        g_w2t_lo[n * HID + k] = lo;
    }
}

// ---------------- count: 8 edges per thread (vector dst loads, MLP=8) -----
__global__ void count_kernel(const void* __restrict__ ei) {
    int t = blockIdx.x * blockDim.x + threadIdx.x;
    if (t >= EE / 8) return;
    int d[8];
    if (g_idx64) {
        const longlong2* p = (const longlong2*)((const long long*)ei + EE) + t * 4;
        longlong2 v0 = p[0], v1 = p[1], v2 = p[2], v3 = p[3];
        d[0] = (int)v0.x; d[1] = (int)v0.y; d[2] = (int)v1.x; d[3] = (int)v1.y;
        d[4] = (int)v2.x; d[5] = (int)v2.y; d[6] = (int)v3.x; d[7] = (int)v3.y;
    } else {
        const int4* p = (const int4*)((const int*)ei + EE) + t * 2;
        int4 v0 = p[0], v1 = p[1];
        d[0] = v0.x; d[1] = v0.y; d[2] = v0.z; d[3] = v0.w;
        d[4] = v1.x; d[5] = v1.y; d[6] = v1.z; d[7] = v1.w;
    }
#pragma unroll
    for (int i = 0; i < 8; i++) atomicAdd(&g_deg[d[i]], 1);
}

// ---------------- scan1: per-block (512) reduce of deg -> g_bsum ----------
__global__ void __launch_bounds__(512, 2) scan1_kernel() {
    __shared__ int ws[16];
    const int lane = threadIdx.x & 31;
    const int wd = threadIdx.x >> 5;
    int i = blockIdx.x * 512 + threadIdx.x;
    int v = (i < NN) ? g_deg[i] : 0;
#pragma unroll
    for (int off = 16; off > 0; off >>= 1) v += __shfl_xor_sync(0xFFFFFFFFu, v, off);
    if (lane == 0) ws[wd] = v;
    __syncthreads();
    if (wd == 0 && lane < 16) {
        int u = ws[lane];
#pragma unroll
        for (int off = 8; off > 0; off >>= 1) u += __shfl_xor_sync(0xFFFFu, u, off);
        if (lane == 0) g_bsum[blockIdx.x] = u;
    }
}

// ---------------- scan2: block offset (redundant) + shfl block scan -------
__global__ void __launch_bounds__(512, 2) scan2_kernel() {
    __shared__ int ws[16];
    __shared__ int sboff;
    const int b = blockIdx.x;
    const int t = threadIdx.x;
    const int lane = t & 31;
    const int wd = t >> 5;

    if (wd == 0) {
        int acc = 0;
#pragma unroll
        for (int base = 0; base < NBLK; base += 32) {
            int idx = base + lane;
            int u = (idx < NBLK && idx < b) ? g_bsum[idx] : 0;
#pragma unroll
            for (int off = 16; off > 0; off >>= 1) u += __shfl_xor_sync(0xFFFFFFFFu, u, off);
            acc += u;
        }
        if (lane == 0) sboff = acc;
    }

    int i = b * 512 + t;
    int v = (i < NN) ? g_deg[i] : 0;
    int s = v;
#pragma unroll
    for (int off = 1; off < 32; off <<= 1) {
        int u = __shfl_up_sync(0xFFFFFFFFu, s, off);
        if (lane >= off) s += u;
    }
    if (lane == 31) ws[wd] = s;
    __syncthreads();
    if (wd == 0 && lane < 16) {
        int u2 = ws[lane];
        int w2 = u2;
#pragma unroll
        for (int off = 1; off < 16; off <<= 1) {
            int uu = __shfl_up_sync(0xFFFFu, w2, off);
            if (lane >= off) w2 += uu;
        }
        ws[lane] = w2 - u2;
    }
    __syncthreads();
    if (i < NN) {
        int excl = sboff + ws[wd] + (s - v);
        g_rowptr[i] = excl;
        g_cursor[i] = excl;
    }
    if (i == 0) g_rowptr[NN] = EE;
}

// ---------------- fill: 4 edges per thread (vector loads, MLP=4) ----------
__global__ void fill_kernel(const void* __restrict__ ei) {
    int t = blockIdx.x * blockDim.x + threadIdx.x;
    if (t >= EE / 4) return;
    int s[4], d[4];
    if (g_idx64) {
        const longlong2* sp = (const longlong2*)ei + t * 2;
        const longlong2* dp = (const longlong2*)((const long long*)ei + EE) + t * 2;
        longlong2 s0 = sp[0], s1 = sp[1], d0 = dp[0], d1 = dp[1];
        s[0] = (int)s0.x; s[1] = (int)s0.y; s[2] = (int)s1.x; s[3] = (int)s1.y;
        d[0] = (int)d0.x; d[1] = (int)d0.y; d[2] = (int)d1.x; d[3] = (int)d1.y;
    } else {
        int4 sv = ((const int4*)ei)[t];
        int4 dv = ((const int4*)((const int*)ei + EE))[t];
        s[0] = sv.x; s[1] = sv.y; s[2] = sv.z; s[3] = sv.w;
        d[0] = dv.x; d[1] = dv.y; d[2] = dv.z; d[3] = dv.w;
    }
    int p[4];
#pragma unroll
    for (int i = 0; i < 4; i++) p[i] = atomicAdd(&g_cursor[d[i]], 1);
#pragma unroll
    for (int i = 0; i < 4; i++) g_csr[p[i]] = s[i];
}

// ---------------- gather1: bf16 hi/lo neighbor reads (256B/edge) ----------
__global__ void gather1_kernel() {
    int w = (blockIdx.x * blockDim.x + threadIdx.x) >> 5;   // node
    int q = threadIdx.x & 31;                               // float4 column
    if (w >= NN) return;
    const uint2* xh = (const uint2*)g_xhi;
    const uint2* xl = (const uint2*)g_xlo;
    size_t sbase = (size_t)w * 32 + q;
    uint2 sh = xh[sbase], sl = xl[sbase];
    float4 acc;
    acc.x = bflo(sh.x) + bflo(sl.x);
    acc.y = bfhi(sh.x) + bfhi(sl.x);
    acc.z = bflo(sh.y) + bflo(sl.y);
    acc.w = bfhi(sh.y) + bfhi(sl.y);
    int beg = g_rowptr[w];
    int end = g_rowptr[w + 1];
#pragma unroll 4
    for (int e = beg; e < end; e++) {
        int j = g_csr[e];
        size_t b = (size_t)j * 32 + q;
        uint2 hv = __ldg(xh + b);
        uint2 lv = __ldg(xl + b);
        acc.x += bflo(hv.x) + bflo(lv.x);
        acc.y += bfhi(hv.x) + bfhi(lv.x);
        acc.z += bflo(hv.y) + bflo(lv.y);
        acc.w += bfhi(hv.y) + bfhi(lv.y);
    }
    float cnt = 1.0f + (float)(end - beg);
    float4 s4 = *(const float4*)(g_s0 + 4 * q);
    float4 t4 = *(const float4*)(g_t0 + 4 * q);
    float a0 = acc.x * s4.x + cnt * t4.x;
    float a1 = acc.y * s4.y + cnt * t4.y;
    float a2 = acc.z * s4.z + cnt * t4.z;
    float a3 = acc.w * s4.w + cnt * t4.w;
    __nv_bfloat16 h0 = __float2bfloat16_rn(a0), h1 = __float2bfloat16_rn(a1);
    __nv_bfloat16 h2 = __float2bfloat16_rn(a2), h3 = __float2bfloat16_rn(a3);
    ushort4 hv, lv;
    hv.x = __bfloat16_as_ushort(h0); hv.y = __bfloat16_as_ushort(h1);
    hv.z = __bfloat16_as_ushort(h2); hv.w = __bfloat16_as_ushort(h3);
    lv.x = __bfloat16_as_ushort(__float2bfloat16_rn(a0 - __bfloat162float(h0)));
    lv.y = __bfloat16_as_ushort(__float2bfloat16_rn(a1 - __bfloat162float(h1)));
    lv.z = __bfloat16_as_ushort(__float2bfloat16_rn(a2 - __bfloat162float(h2)));
    lv.w = __bfloat16_as_ushort(__float2bfloat16_rn(a3 - __bfloat162float(h3)));
    size_t base = (size_t)w * FIN + 4 * q;
    *(ushort4*)(g_ahi + base) = hv;
    *(ushort4*)(g_alo + base) = lv;
}

// ---------------- GEMM1: mma.sync bf16x3, 128x256 tile per CTA ------------
// smem: Ah(32K) | Al(32K) | Bh(64K) | Bl(64K) = 192KB, XOR-swizzled rows
#define G1_SMEM 196608

__global__ void __launch_bounds__(256, 1) gemm1_kernel() {
    __shared__ float sc1[256], dc1[256];

    const int tid = threadIdx.x;
    const int wid = tid >> 5;
    const int lid = tid & 31;
    const int mBase = blockIdx.x * 128;
    const unsigned sbase = smem_u32(dyn_smem);

    sc1[tid] = g_s1[tid];
    dc1[tid] = g_d1[tid];

    {
        int row = tid >> 1;
        int half = tid & 1;
        const uint4* ah = (const uint4*)(g_ahi + (size_t)(mBase + row) * FIN);
        const uint4* al = (const uint4*)(g_alo + (size_t)(mBase + row) * FIN);
#pragma unroll
        for (int i = 0; i < 8; i++) {
            int c = half * 8 + i;
            unsigned off = row * 256 + ((unsigned)(c ^ (row & 7))) * 16;
            *(uint4*)(dyn_smem + off) = ah[c];
            *(uint4*)(dyn_smem + 32768 + off) = al[c];
        }
    }
    {
        const uint4* bh = (const uint4*)(g_w1t_hi + (size_t)tid * FIN);
        const uint4* bl = (const uint4*)(g_w1t_lo + (size_t)tid * FIN);
#pragma unroll
        for (int c = 0; c < 16; c++) {
            unsigned off = tid * 256 + ((unsigned)(c ^ (tid & 7))) * 16;
            *(uint4*)(dyn_smem + 65536 + off) = bh[c];
            *(uint4*)(dyn_smem + 131072 + off) = bl[c];
        }
    }
    __syncthreads();

    const int wm = (wid >> 2) * 64;
    const int wn = (wid & 3) * 64;

    float acc[4][8][4];
#pragma unroll
    for (int mt = 0; mt < 4; mt++)
#pragma unroll
        for (int nt = 0; nt < 8; nt++)
#pragma unroll
            for (int r = 0; r < 4; r++) acc[mt][nt][r] = 0.0f;

    const int a_r = lid & 15;
    const int a_c = lid >> 4;
    const int b_r = (lid & 7) + ((lid >> 4) << 3);
    const int b_c = (lid >> 3) & 1;

#pragma unroll
    for (int pass = 0; pass < 3; pass++) {
        unsigned Ab = sbase + ((pass == 2) ? 32768u : 0u);
        unsigned Bb = sbase + 65536u + ((pass == 1) ? 65536u : 0u);
#pragma unroll
        for (int ks = 0; ks < 8; ks++) {
            unsigned a[4][4];
#pragma unroll
            for (int mt = 0; mt < 4; mt++) {
                int row = wm + mt * 16 + a_r;
                int c = ks * 2 + a_c;
                ldsm4(a[mt], Ab + row * 256 + ((unsigned)(c ^ (row & 7))) * 16);
            }
            unsigned b[8][2];
#pragma unroll
            for (int bt = 0; bt < 4; bt++) {
                int row = wn + bt * 16 + b_r;
                int c = ks * 2 + b_c;
                unsigned bb[4];
                ldsm4(bb, Bb + row * 256 + ((unsigned)(c ^ (row & 7))) * 16);
                b[bt * 2 + 0][0] = bb[0]; b[bt * 2 + 0][1] = bb[1];
                b[bt * 2 + 1][0] = bb[2]; b[bt * 2 + 1][1] = bb[3];
            }
#pragma unroll
            for (int mt = 0; mt < 4; mt++)
#pragma unroll
                for (int nt = 0; nt < 8; nt++)
                    mma_bf16(acc[mt][nt], a[mt], b[nt]);
        }
    }

    const int rbase = lid >> 2;
    const int cbase = (lid & 3) * 2;
#pragma unroll
    for (int mt = 0; mt < 4; mt++) {
#pragma unroll
        for (int nt = 0; nt < 8; nt++) {
            int n0 = wn + nt * 8 + cbase;
            float s0c = sc1[n0], s1c = sc1[n0 + 1];
            float d0c = dc1[n0], d1c = dc1[n0 + 1];
            int m0 = mBase + wm + mt * 16 + rbase;
#pragma unroll
            for (int half = 0; half < 2; half++) {
                float v0 = fmaxf(acc[mt][nt][half * 2 + 0] * s0c + d0c, 0.0f);
                float v1 = fmaxf(acc[mt][nt][half * 2 + 1] * s1c + d1c, 0.0f);
                unsigned hp = packbf2(v0, v1);
                float h0f = __bfloat162float(__ushort_as_bfloat16((unsigned short)(hp & 0xFFFF)));
                float h1f = __bfloat162float(__ushort_as_bfloat16((unsigned short)(hp >> 16)));
                unsigned lp = packbf2(v0 - h0f, v1 - h1f);
                size_t idx = (size_t)(m0 + half * 8) * HID + n0;
                *(unsigned*)(g_h1hi + idx) = hp;
                *(unsigned*)(g_h1lo + idx) = lp;
            }
        }
    }
}

// ---------------- GEMM2: mma.sync bf16x3, 256x40 tile per CTA -------------
#define G2_SMEM 91648
#define G2_BH 0
#define G2_BL 25344
#define G2_AH 50688
#define G2_AL 71168

__global__ void __launch_bounds__(256, 2) gemm2_kernel() {
    const int tid = threadIdx.x;
    const int wid = tid >> 5;
    const int lid = tid & 31;
    const int mBase = blockIdx.x * 256;
    const unsigned sb = smem_u32(dyn_smem);

    for (int l = tid; l < 48 * 32; l += 256) {
        int row = l >> 5;
        int c = l & 31;
        unsigned off = row * 528 + c * 16;
        *(uint4*)(dyn_smem + G2_BH + off) = *(const uint4*)((const char*)g_w2t_hi + row * 512 + c * 16);
        *(uint4*)(dyn_smem + G2_BL + off) = *(const uint4*)((const char*)g_w2t_lo + row * 512 + c * 16);
    }

    const int a_r = lid & 15;
    const int a_c = lid >> 4;
    const int b_r = (lid & 7) + ((lid >> 4) << 3);
    const int b_c = (lid >> 3) & 1;
    const int wm = wid * 32;

    float acc[2][5][4];
#pragma unroll
    for (int mt = 0; mt < 2; mt++)
#pragma unroll
        for (int nt = 0; nt < 5; nt++)
#pragma unroll
            for (int r = 0; r < 4; r++) acc[mt][nt][r] = 0.0f;

    for (int kc = 0; kc < 8; kc++) {
        __syncthreads();
#pragma unroll
        for (int i = 0; i < 4; i++) {
            int l = tid + 256 * i;
            int row = l >> 2;
            int c = l & 3;
            unsigned off = row * 80 + c * 16;
            size_t gidx = (size_t)(mBase + row) * HID + kc * 32 + c * 8;
            *(uint4*)(dyn_smem + G2_AH + off) = *(const uint4*)(g_h1hi + gidx);
            *(uint4*)(dyn_smem + G2_AL + off) = *(const uint4*)(g_h1lo + gidx);
        }
        __syncthreads();

#pragma unroll
        for (int ks = 0; ks < 2; ks++) {
            unsigned ah[2][4], al[2][4];
#pragma unroll
            for (int mt = 0; mt < 2; mt++) {
                int row = wm + mt * 16 + a_r;
                unsigned off = row * 80 + (unsigned)(ks * 2 + a_c) * 16;
                ldsm4(ah[mt], sb + G2_AH + off);
                ldsm4(al[mt], sb + G2_AL + off);
            }
            unsigned bh[6][2], bl[6][2];
#pragma unroll
            for (int bt = 0; bt < 3; bt++) {
                int row = bt * 16 + b_r;
                unsigned off = row * 528 + (unsigned)(kc * 4 + ks * 2 + b_c) * 16;
                unsigned t0[4], t1[4];
                ldsm4(t0, sb + G2_BH + off);
                ldsm4(t1, sb + G2_BL + off);
                bh[bt * 2 + 0][0] = t0[0]; bh[bt * 2 + 0][1] = t0[1];
                bh[bt * 2 + 1][0] = t0[2]; bh[bt * 2 + 1][1] = t0[3];
                bl[bt * 2 + 0][0] = t1[0]; bl[bt * 2 + 0][1] = t1[1];
                bl[bt * 2 + 1][0] = t1[2]; bl[bt * 2 + 1][1] = t1[3];
            }
#pragma unroll
            for (int mt = 0; mt < 2; mt++)
#pragma unroll
                for (int nt = 0; nt < 5; nt++) {
                    mma_bf16(acc[mt][nt], ah[mt], bh[nt]);
                    mma_bf16(acc[mt][nt], ah[mt], bl[nt]);
                    mma_bf16(acc[mt][nt], al[mt], bh[nt]);
                }
        }
    }

    const int rbase = lid >> 2;
    const int cbase = (lid & 3) * 2;
#pragma unroll
    for (int mt = 0; mt < 2; mt++) {
#pragma unroll
        for (int nt = 0; nt < 5; nt++) {
            int n0 = nt * 8 + cbase;
            int m0 = mBase + wm + mt * 16 + rbase;
            if (m0 < NN) {
                float2 v = make_float2(acc[mt][nt][0], acc[mt][nt][1]);
                *(float2*)(g_y + m0 * NCLS + n0) = v;
            }
            if (m0 + 8 < NN) {
                float2 v = make_float2(acc[mt][nt][2], acc[mt][nt][3]);
                *(float2*)(g_y + (m0 + 8) * NCLS + n0) = v;
            }
        }
    }
}

// ---------------- gather2: out[i] = b2 + y[i] + sum y[j] ------------------
__global__ void gather2_kernel(const float* __restrict__ b2, float* __restrict__ out) {
    int h = (blockIdx.x * blockDim.x + threadIdx.x) >> 4;
    int q = threadIdx.x & 15;
    if (h >= NN || q >= 10) return;
    const float4* yb = (const float4*)g_y;
    float4 acc = __ldg((const float4*)b2 + q);
    float4 v = yb[(size_t)h * 10 + q];
    acc.x += v.x; acc.y += v.y; acc.z += v.z; acc.w += v.w;
    int beg = g_rowptr[h];
    int end = g_rowptr[h + 1];
#pragma unroll 4
    for (int e = beg; e < end; e++) {
        int j = g_csr[e];
        float4 u = __ldg(yb + (size_t)j * 10 + q);
        acc.x += u.x; acc.y += u.y; acc.z += u.z; acc.w += u.w;
    }
    ((float4*)out)[(size_t)h * 10 + q] = acc;
}

// --------------------------------------------------------------------------
extern "C" void kernel_launch(void* const* d_in, const int* in_sizes, int n_in,
                              void* d_out, int out_size) {
    const float* x    = (const float*)d_in[0];
    const void*  ei   = d_in[1];
    const float* bn0g = (const float*)d_in[2];
    const float* bn0b = (const float*)d_in[3];
    const float* bn0m = (const float*)d_in[4];
    const float* bn0v = (const float*)d_in[5];
    const float* W1   = (const float*)d_in[6];
    const float* b1   = (const float*)d_in[7];
    const float* bn1g = (const float*)d_in[8];
    const float* bn1b = (const float*)d_in[9];
    const float* bn1m = (const float*)d_in[10];
    const float* bn1v = (const float*)d_in[11];
    const float* W2   = (const float*)d_in[12];
    const float* b2   = (const float*)d_in[13];
    float* out = (float*)d_out;

    cudaFuncSetAttribute(gemm1_kernel, cudaFuncAttributeMaxDynamicSharedMemorySize,
                         G1_SMEM);
    cudaFuncSetAttribute(gemm2_kernel, cudaFuncAttributeMaxDynamicSharedMemorySize,
                         G2_SMEM);

    init_kernel<<<(NN * (FIN / 4) + 255) / 256, 256>>>(x, (const unsigned int*)ei,
                                                       bn0g, bn0b, bn0m, bn0v, W1, b1,
                                                       bn1g, bn1b, bn1m, bn1v, W2);
    count_kernel<<<(EE / 8 + 255) / 256, 256>>>(ei);
    scan1_kernel<<<NBLK, 512>>>();
    scan2_kernel<<<NBLK, 512>>>();
    fill_kernel<<<(EE / 4 + 255) / 256, 256>>>(ei);
    gather1_kernel<<<(NN * 32 + 255) / 256, 256>>>();
    gemm1_kernel<<<NNP / 128, 256, G1_SMEM>>>();
    gemm2_kernel<<<NNP / 256, 256, G2_SMEM>>>();
    gather2_kernel<<<(NN * 16 + 255) / 256, 256>>>(b2, out);
}

// round 16
// speedup vs baseline: 1.0636x; 1.0636x over previous
#include <cuda_runtime.h>
#include <cuda_bf16.h>

#define NN   50000
#define NNP  50176              // padded to multiple of 256
#define FIN  128
#define HID  256
#define NCLS 40
#define EE   600000
#define BN_EPS 1e-5f
#define NBLK 98                 // scan blocks: 98*512 = 50176 >= NN

// ---------------- device scratch (zero-initialized, no allocs) -----------
__device__ __nv_bfloat16 g_ahi[(size_t)NNP * FIN];   // hi(BN0-folded agg1)
__device__ __nv_bfloat16 g_alo[(size_t)NNP * FIN];   // lo residual
__device__ __nv_bfloat16 g_w1t_hi[HID * FIN];        // W1^T hi  [n][k]
__device__ __nv_bfloat16 g_w1t_lo[HID * FIN];        // W1^T lo
__device__ __nv_bfloat16 g_w2t_hi[48 * HID];         // W2^T hi [n][k], n pad 48
__device__ __nv_bfloat16 g_w2t_lo[48 * HID];         // W2^T lo
__device__ __nv_bfloat16 g_h1hi[(size_t)NNP * HID];  // h1 hi
__device__ __nv_bfloat16 g_h1lo[(size_t)NNP * HID];  // h1 lo
__device__ float g_s0[FIN], g_t0[FIN];               // BN0 affine
__device__ float g_s1[HID], g_d1[HID];               // BN1 scale, b1*s1+t1
__device__ int   g_deg[NN];
__device__ int   g_rowptr[NN + 1];
__device__ int   g_cursor[NN];
__device__ int   g_csr[EE];
__device__ float g_y[NN * NCLS];
__device__ int   g_idx64;

// ---------------- mma.sync / ldmatrix helpers (base ISA) ------------------
__device__ __forceinline__ unsigned smem_u32(const void* p) {
    unsigned a;
    asm("{ .reg .u64 t; cvta.to.shared.u64 t, %1; cvt.u32.u64 %0, t; }" : "=r"(a) : "l"(p));
    return a;
}
__device__ __forceinline__ void ldsm4(unsigned* r, unsigned addr) {
    asm volatile("ldmatrix.sync.aligned.m8n8.x4.shared.b16 {%0,%1,%2,%3}, [%4];"
                 : "=r"(r[0]), "=r"(r[1]), "=r"(r[2]), "=r"(r[3]) : "r"(addr));
}
__device__ __forceinline__ void mma_bf16(float* d, const unsigned* a, const unsigned* b) {
    asm volatile(
        "mma.sync.aligned.m16n8k16.row.col.f32.bf16.bf16.f32 "
        "{%0,%1,%2,%3}, {%4,%5,%6,%7}, {%8,%9}, {%0,%1,%2,%3};"
        : "+f"(d[0]), "+f"(d[1]), "+f"(d[2]), "+f"(d[3])
        : "r"(a[0]), "r"(a[1]), "r"(a[2]), "r"(a[3]), "r"(b[0]), "r"(b[1]));
}
__device__ __forceinline__ unsigned packbf2(float a, float b) {
    unsigned r;
    asm("cvt.rn.satfinite.bf16x2.f32 %0, %1, %2;" : "=r"(r) : "f"(b), "f"(a));
    return r;
}

extern __shared__ char dyn_smem[];

// ---------------- init: detect dtype + zero deg + BN affines + W splits ---
__global__ void init_kernel(const unsigned int* __restrict__ ei,
                            const float* __restrict__ bn0g, const float* __restrict__ bn0b,
                            const float* __restrict__ bn0m, const float* __restrict__ bn0v,
                            const float* __restrict__ W1, const float* __restrict__ b1,
                            const float* __restrict__ bn1g, const float* __restrict__ bn1b,
                            const float* __restrict__ bn1m, const float* __restrict__ bn1v,
                            const float* __restrict__ W2) {
    int t = blockIdx.x * blockDim.x + threadIdx.x;
    if (t < NN) g_deg[t] = 0;
    if (blockIdx.x == 0 && threadIdx.x < 32) {
        int l = threadIdx.x;
        unsigned any = 0;
        for (int k = l; k < 1024; k += 32) any |= ei[2 * k + 1];
#pragma unroll
        for (int off = 16; off > 0; off >>= 1) any |= __shfl_xor_sync(0xFFFFFFFFu, any, off);
        if (l == 0) g_idx64 = (any == 0) ? 1 : 0;
    }
    if (t < FIN) {
        float s0 = bn0g[t] * rsqrtf(bn0v[t] + BN_EPS);
        g_s0[t] = s0;
        g_t0[t] = bn0b[t] - bn0m[t] * s0;
    }
    if (t < HID) {
        float s1 = bn1g[t] * rsqrtf(bn1v[t] + BN_EPS);
        g_s1[t] = s1;
        g_d1[t] = b1[t] * s1 + (bn1b[t] - bn1m[t] * s1);
    }
    if (t < FIN * HID) {
        int k = t / HID;
        int n = t % HID;
        float w = W1[t];
        __nv_bfloat16 hi = __float2bfloat16_rn(w);
        __nv_bfloat16 lo = __float2bfloat16_rn(w - __bfloat162float(hi));
        g_w1t_hi[n * FIN + k] = hi;
        g_w1t_lo[n * FIN + k] = lo;
    }
    if (t < HID * NCLS) {
        int k = t / NCLS;
        int n = t % NCLS;
        float w = W2[t];
        __nv_bfloat16 hi = __float2bfloat16_rn(w);
        __nv_bfloat16 lo = __float2bfloat16_rn(w - __bfloat162float(hi));
        g_w2t_hi[n * HID + k] = hi;
        g_w2t_lo[n * HID + k] = lo;
    }
}

// ---------------- count: 8 edges per thread (vector dst loads, MLP=8) -----
__global__ void count_kernel(const void* __restrict__ ei) {
    int t = blockIdx.x * blockDim.x + threadIdx.x;
    if (t >= EE / 8) return;
    int d[8];
    if (g_idx64) {
        const longlong2* p = (const longlong2*)((const long long*)ei + EE) + t * 4;
        longlong2 v0 = p[0], v1 = p[1], v2 = p[2], v3 = p[3];
        d[0] = (int)v0.x; d[1] = (int)v0.y; d[2] = (int)v1.x; d[3] = (int)v1.y;
        d[4] = (int)v2.x; d[5] = (int)v2.y; d[6] = (int)v3.x; d[7] = (int)v3.y;
    } else {
        const int4* p = (const int4*)((const int*)ei + EE) + t * 2;
        int4 v0 = p[0], v1 = p[1];
        d[0] = v0.x; d[1] = v0.y; d[2] = v0.z; d[3] = v0.w;
        d[4] = v1.x; d[5] = v1.y; d[6] = v1.z; d[7] = v1.w;
    }
#pragma unroll
    for (int i = 0; i < 8; i++) atomicAdd(&g_deg[d[i]], 1);
}

// ---------------- scan (fused): each block redundantly computes its -------
// offset by summing deg[0 .. b*512), then shfl block scan + writeback.
__global__ void __launch_bounds__(512, 2) scan_kernel() {
    __shared__ int rs[16];      // reduce scratch (block offset)
    __shared__ int ws[16];      // scan scratch (warp prefixes)
    __shared__ int sboff;
    const int b = blockIdx.x;
    const int t = threadIdx.x;
    const int lane = t & 31;
    const int wd = t >> 5;

    // ---- block offset: coalesced strided sum of deg[0 .. b*512) ----
    int pre = 0;
    const int limit = b * 512;
    for (int i = t; i < limit; i += 512) pre += g_deg[i];
#pragma unroll
    for (int off = 16; off > 0; off >>= 1) pre += __shfl_xor_sync(0xFFFFFFFFu, pre, off);
    if (lane == 0) rs[wd] = pre;
    __syncthreads();
    if (wd == 0 && lane < 16) {
        int u = rs[lane];
#pragma unroll
        for (int off = 8; off > 0; off >>= 1) u += __shfl_xor_sync(0xFFFFu, u, off);
        if (lane == 0) sboff = u;
    }

    // ---- block-local exclusive scan of this block's 512 deg values ----
    int i = b * 512 + t;
    int v = (i < NN) ? g_deg[i] : 0;
    int s = v;
#pragma unroll
    for (int off = 1; off < 32; off <<= 1) {
        int u = __shfl_up_sync(0xFFFFFFFFu, s, off);
        if (lane >= off) s += u;
    }
    if (lane == 31) ws[wd] = s;
    __syncthreads();
    if (wd == 0 && lane < 16) {
        int u2 = ws[lane];
        int w2 = u2;
#pragma unroll
        for (int off = 1; off < 16; off <<= 1) {
            int uu = __shfl_up_sync(0xFFFFu, w2, off);
            if (lane >= off) w2 += uu;
        }
        ws[lane] = w2 - u2;                 // exclusive warp offsets
    }
    __syncthreads();
    if (i < NN) {
        int excl = sboff + ws[wd] + (s - v);
        g_rowptr[i] = excl;
        g_cursor[i] = excl;
    }
    if (i == 0) g_rowptr[NN] = EE;          // total is edge count by construction
}

// ---------------- fill: 4 edges per thread (vector loads, MLP=4) ----------
__global__ void fill_kernel(const void* __restrict__ ei) {
    int t = blockIdx.x * blockDim.x + threadIdx.x;
    if (t >= EE / 4) return;
    int s[4], d[4];
    if (g_idx64) {
        const longlong2* sp = (const longlong2*)ei + t * 2;
        const longlong2* dp = (const longlong2*)((const long long*)ei + EE) + t * 2;
        longlong2 s0 = sp[0], s1 = sp[1], d0 = dp[0], d1 = dp[1];
        s[0] = (int)s0.x; s[1] = (int)s0.y; s[2] = (int)s1.x; s[3] = (int)s1.y;
        d[0] = (int)d0.x; d[1] = (int)d0.y; d[2] = (int)d1.x; d[3] = (int)d1.y;
    } else {
        int4 sv = ((const int4*)ei)[t];
        int4 dv = ((const int4*)((const int*)ei + EE))[t];
        s[0] = sv.x; s[1] = sv.y; s[2] = sv.z; s[3] = sv.w;
        d[0] = dv.x; d[1] = dv.y; d[2] = dv.z; d[3] = dv.w;
    }
    int p[4];
#pragma unroll
    for (int i = 0; i < 4; i++) p[i] = atomicAdd(&g_cursor[d[i]], 1);
#pragma unroll
    for (int i = 0; i < 4; i++) g_csr[p[i]] = s[i];
}

// ---------------- gather1: BN0-folded agg, split to bf16 hi/lo ------------
__global__ void gather1_kernel(const float* __restrict__ x) {
    int w = (blockIdx.x * blockDim.x + threadIdx.x) >> 5;   // node
    int q = threadIdx.x & 31;                               // float4 column
    if (w >= NN) return;
    const float4* xb = (const float4*)x;
    float4 acc = __ldg(xb + (size_t)w * 32 + q);
    int beg = g_rowptr[w];
    int end = g_rowptr[w + 1];
#pragma unroll 4
    for (int e = beg; e < end; e++) {
        int j = g_csr[e];
        float4 v = __ldg(xb + (size_t)j * 32 + q);
        acc.x += v.x; acc.y += v.y; acc.z += v.z; acc.w += v.w;
    }
    float cnt = 1.0f + (float)(end - beg);
    float4 s4 = *(const float4*)(g_s0 + 4 * q);
    float4 t4 = *(const float4*)(g_t0 + 4 * q);
    float a0 = acc.x * s4.x + cnt * t4.x;
    float a1 = acc.y * s4.y + cnt * t4.y;
    float a2 = acc.z * s4.z + cnt * t4.z;
    float a3 = acc.w * s4.w + cnt * t4.w;
    __nv_bfloat16 h0 = __float2bfloat16_rn(a0), h1 = __float2bfloat16_rn(a1);
    __nv_bfloat16 h2 = __float2bfloat16_rn(a2), h3 = __float2bfloat16_rn(a3);
    ushort4 hv, lv;
    hv.x = __bfloat16_as_ushort(h0); hv.y = __bfloat16_as_ushort(h1);
    hv.z = __bfloat16_as_ushort(h2); hv.w = __bfloat16_as_ushort(h3);
    lv.x = __bfloat16_as_ushort(__float2bfloat16_rn(a0 - __bfloat162float(h0)));
    lv.y = __bfloat16_as_ushort(__float2bfloat16_rn(a1 - __bfloat162float(h1)));
    lv.z = __bfloat16_as_ushort(__float2bfloat16_rn(a2 - __bfloat162float(h2)));
    lv.w = __bfloat16_as_ushort(__float2bfloat16_rn(a3 - __bfloat162float(h3)));
    size_t base = (size_t)w * FIN + 4 * q;
    *(ushort4*)(g_ahi + base) = hv;
    *(ushort4*)(g_alo + base) = lv;
}

// ---------------- GEMM1: mma.sync bf16x3, 128x256 tile per CTA ------------
// smem: Ah(32K) | Al(32K) | Bh(64K) | Bl(64K) = 192KB, XOR-swizzled rows
#define G1_SMEM 196608

__global__ void __launch_bounds__(256, 1) gemm1_kernel() {
    __shared__ float sc1[256], dc1[256];

    const int tid = threadIdx.x;
    const int wid = tid >> 5;
    const int lid = tid & 31;
    const int mBase = blockIdx.x * 128;
    const unsigned sbase = smem_u32(dyn_smem);

    sc1[tid] = g_s1[tid];
    dc1[tid] = g_d1[tid];

    // ---- load A tiles: thread t -> row t/2, chunks (t&1)*8 .. +7 ----
    {
        int row = tid >> 1;
        int half = tid & 1;
        const uint4* ah = (const uint4*)(g_ahi + (size_t)(mBase + row) * FIN);
        const uint4* al = (const uint4*)(g_alo + (size_t)(mBase + row) * FIN);
#pragma unroll
        for (int i = 0; i < 8; i++) {
            int c = half * 8 + i;
            unsigned off = row * 256 + ((unsigned)(c ^ (row & 7))) * 16;
            *(uint4*)(dyn_smem + off) = ah[c];
            *(uint4*)(dyn_smem + 32768 + off) = al[c];
        }
    }
    // ---- load B tiles: thread t -> W1^T row t, all 16 chunks ----
    {
        const uint4* bh = (const uint4*)(g_w1t_hi + (size_t)tid * FIN);
        const uint4* bl = (const uint4*)(g_w1t_lo + (size_t)tid * FIN);
#pragma unroll
        for (int c = 0; c < 16; c++) {
            unsigned off = tid * 256 + ((unsigned)(c ^ (tid & 7))) * 16;
            *(uint4*)(dyn_smem + 65536 + off) = bh[c];
            *(uint4*)(dyn_smem + 131072 + off) = bl[c];
        }
    }
    __syncthreads();

    const int wm = (wid >> 2) * 64;    // warp M offset (0 or 64)
    const int wn = (wid & 3) * 64;     // warp N offset (0,64,128,192)

    float acc[4][8][4];
#pragma unroll
    for (int mt = 0; mt < 4; mt++)
#pragma unroll
        for (int nt = 0; nt < 8; nt++)
#pragma unroll
            for (int r = 0; r < 4; r++) acc[mt][nt][r] = 0.0f;

    const int a_r = lid & 15;
    const int a_c = lid >> 4;
    const int b_r = (lid & 7) + ((lid >> 4) << 3);
    const int b_c = (lid >> 3) & 1;

#pragma unroll
    for (int pass = 0; pass < 3; pass++) {
        unsigned Ab = sbase + ((pass == 2) ? 32768u : 0u);
        unsigned Bb = sbase + 65536u + ((pass == 1) ? 65536u : 0u);
#pragma unroll
        for (int ks = 0; ks < 8; ks++) {
            unsigned a[4][4];
#pragma unroll
            for (int mt = 0; mt < 4; mt++) {
                int row = wm + mt * 16 + a_r;
                int c = ks * 2 + a_c;
                ldsm4(a[mt], Ab + row * 256 + ((unsigned)(c ^ (row & 7))) * 16);
            }
            unsigned b[8][2];
#pragma unroll
            for (int bt = 0; bt < 4; bt++) {
                int row = wn + bt * 16 + b_r;
                int c = ks * 2 + b_c;
                unsigned bb[4];
                ldsm4(bb, Bb + row * 256 + ((unsigned)(c ^ (row & 7))) * 16);
                b[bt * 2 + 0][0] = bb[0]; b[bt * 2 + 0][1] = bb[1];
                b[bt * 2 + 1][0] = bb[2]; b[bt * 2 + 1][1] = bb[3];
            }
#pragma unroll
            for (int mt = 0; mt < 4; mt++)
#pragma unroll
                for (int nt = 0; nt < 8; nt++)
                    mma_bf16(acc[mt][nt], a[mt], b[nt]);
        }
    }

    // ---- epilogue: h = max(d*s1 + (b1*s1+t1), 0), split to bf16 hi/lo ----
    const int rbase = lid >> 2;
    const int cbase = (lid & 3) * 2;
#pragma unroll
    for (int mt = 0; mt < 4; mt++) {
#pragma unroll
        for (int nt = 0; nt < 8; nt++) {
            int n0 = wn + nt * 8 + cbase;
            float s0c = sc1[n0], s1c = sc1[n0 + 1];
            float d0c = dc1[n0], d1c = dc1[n0 + 1];
            int m0 = mBase + wm + mt * 16 + rbase;
#pragma unroll
            for (int half = 0; half < 2; half++) {
                float v0 = fmaxf(acc[mt][nt][half * 2 + 0] * s0c + d0c, 0.0f);
                float v1 = fmaxf(acc[mt][nt][half * 2 + 1] * s1c + d1c, 0.0f);
                unsigned hp = packbf2(v0, v1);
                float h0f = __bfloat162float(__ushort_as_bfloat16((unsigned short)(hp & 0xFFFF)));
                float h1f = __bfloat162float(__ushort_as_bfloat16((unsigned short)(hp >> 16)));
                unsigned lp = packbf2(v0 - h0f, v1 - h1f);
                size_t idx = (size_t)(m0 + half * 8) * HID + n0;
                *(unsigned*)(g_h1hi + idx) = hp;
                *(unsigned*)(g_h1lo + idx) = lp;
            }
        }
    }
}

// ---------------- GEMM2: mma.sync bf16x3, 256x40 tile per CTA -------------
#define G2_SMEM 91648
#define G2_BH 0
#define G2_BL 25344
#define G2_AH 50688
#define G2_AL 71168

__global__ void __launch_bounds__(256, 2) gemm2_kernel() {
    const int tid = threadIdx.x;
    const int wid = tid >> 5;
    const int lid = tid & 31;
    const int mBase = blockIdx.x * 256;
    const unsigned sb = smem_u32(dyn_smem);

    for (int l = tid; l < 48 * 32; l += 256) {
        int row = l >> 5;
        int c = l & 31;
        unsigned off = row * 528 + c * 16;
        *(uint4*)(dyn_smem + G2_BH + off) = *(const uint4*)((const char*)g_w2t_hi + row * 512 + c * 16);
        *(uint4*)(dyn_smem + G2_BL + off) = *(const uint4*)((const char*)g_w2t_lo + row * 512 + c * 16);
    }

    const int a_r = lid & 15;
    const int a_c = lid >> 4;
    const int b_r = (lid & 7) + ((lid >> 4) << 3);
    const int b_c = (lid >> 3) & 1;
    const int wm = wid * 32;

    float acc[2][5][4];
#pragma unroll
    for (int mt = 0; mt < 2; mt++)
#pragma unroll
        for (int nt = 0; nt < 5; nt++)
#pragma unroll
            for (int r = 0; r < 4; r++) acc[mt][nt][r] = 0.0f;

    for (int kc = 0; kc < 8; kc++) {
        __syncthreads();
#pragma unroll
        for (int i = 0; i < 4; i++) {
            int l = tid + 256 * i;
            int row = l >> 2;
            int c = l & 3;
            unsigned off = row * 80 + c * 16;
            size_t gidx = (size_t)(mBase + row) * HID + kc * 32 + c * 8;
            *(uint4*)(dyn_smem + G2_AH + off) = *(const uint4*)(g_h1hi + gidx);
            *(uint4*)(dyn_smem + G2_AL + off) = *(const uint4*)(g_h1lo + gidx);
        }
        __syncthreads();

#pragma unroll
        for (int ks = 0; ks < 2; ks++) {
            unsigned ah[2][4], al[2][4];
#pragma unroll
            for (int mt = 0; mt < 2; mt++) {
                int row = wm + mt * 16 + a_r;
                unsigned off = row * 80 + (unsigned)(ks * 2 + a_c) * 16;
                ldsm4(ah[mt], sb + G2_AH + off);
                ldsm4(al[mt], sb + G2_AL + off);
            }
            unsigned bh[6][2], bl[6][2];
#pragma unroll
            for (int bt = 0; bt < 3; bt++) {
                int row = bt * 16 + b_r;
                unsigned off = row * 528 + (unsigned)(kc * 4 + ks * 2 + b_c) * 16;
                unsigned t0[4], t1[4];
                ldsm4(t0, sb + G2_BH + off);
                ldsm4(t1, sb + G2_BL + off);
                bh[bt * 2 + 0][0] = t0[0]; bh[bt * 2 + 0][1] = t0[1];
                bh[bt * 2 + 1][0] = t0[2]; bh[bt * 2 + 1][1] = t0[3];
                bl[bt * 2 + 0][0] = t1[0]; bl[bt * 2 + 0][1] = t1[1];
                bl[bt * 2 + 1][0] = t1[2]; bl[bt * 2 + 1][1] = t1[3];
            }
#pragma unroll
            for (int mt = 0; mt < 2; mt++)
#pragma unroll
                for (int nt = 0; nt < 5; nt++) {
                    mma_bf16(acc[mt][nt], ah[mt], bh[nt]);
                    mma_bf16(acc[mt][nt], ah[mt], bl[nt]);
                    mma_bf16(acc[mt][nt], al[mt], bh[nt]);
                }
        }
    }

    const int rbase = lid >> 2;
    const int cbase = (lid & 3) * 2;
#pragma unroll
    for (int mt = 0; mt < 2; mt++) {
#pragma unroll
        for (int nt = 0; nt < 5; nt++) {
            int n0 = nt * 8 + cbase;
            int m0 = mBase + wm + mt * 16 + rbase;
            if (m0 < NN) {
                float2 v = make_float2(acc[mt][nt][0], acc[mt][nt][1]);
                *(float2*)(g_y + m0 * NCLS + n0) = v;
            }
            if (m0 + 8 < NN) {
                float2 v = make_float2(acc[mt][nt][2], acc[mt][nt][3]);
                *(float2*)(g_y + (m0 + 8) * NCLS + n0) = v;
            }
        }
    }
}

// ---------------- gather2: out[i] = b2 + y[i] + sum y[j] ------------------
__global__ void gather2_kernel(const float* __restrict__ b2, float* __restrict__ out) {
    int h = (blockIdx.x * blockDim.x + threadIdx.x) >> 4;
    int q = threadIdx.x & 15;
    if (h >= NN || q >= 10) return;
    const float4* yb = (const float4*)g_y;
    float4 acc = __ldg((const float4*)b2 + q);
    float4 v = yb[(size_t)h * 10 + q];
    acc.x += v.x; acc.y += v.y; acc.z += v.z; acc.w += v.w;
    int beg = g_rowptr[h];
    int end = g_rowptr[h + 1];
#pragma unroll 4
    for (int e = beg; e < end; e++) {
        int j = g_csr[e];
        float4 u = __ldg(yb + (size_t)j * 10 + q);
        acc.x += u.x; acc.y += u.y; acc.z += u.z; acc.w += u.w;
    }
    ((float4*)out)[(size_t)h * 10 + q] = acc;
}

// --------------------------------------------------------------------------
extern "C" void kernel_launch(void* const* d_in, const int* in_sizes, int n_in,
                              void* d_out, int out_size) {
    const float* x    = (const float*)d_in[0];
    const void*  ei   = d_in[1];
    const float* bn0g = (const float*)d_in[2];
    const float* bn0b = (const float*)d_in[3];
    const float* bn0m = (const float*)d_in[4];
    const float* bn0v = (const float*)d_in[5];
    const float* W1   = (const float*)d_in[6];
    const float* b1   = (const float*)d_in[7];
    const float* bn1g = (const float*)d_in[8];
    const float* bn1b = (const float*)d_in[9];
    const float* bn1m = (const float*)d_in[10];
    const float* bn1v = (const float*)d_in[11];
    const float* W2   = (const float*)d_in[12];
    const float* b2   = (const float*)d_in[13];
    float* out = (float*)d_out;

    cudaFuncSetAttribute(gemm1_kernel, cudaFuncAttributeMaxDynamicSharedMemorySize,
                         G1_SMEM);
    cudaFuncSetAttribute(gemm2_kernel, cudaFuncAttributeMaxDynamicSharedMemorySize,
                         G2_SMEM);

    init_kernel<<<(NN + 255) / 256, 256>>>((const unsigned int*)ei,
                                           bn0g, bn0b, bn0m, bn0v, W1, b1,
                                           bn1g, bn1b, bn1m, bn1v, W2);
    count_kernel<<<(EE / 8 + 255) / 256, 256>>>(ei);
    scan_kernel<<<NBLK, 512>>>();
    fill_kernel<<<(EE / 4 + 255) / 256, 256>>>(ei);
    gather1_kernel<<<(NN * 32 + 255) / 256, 256>>>(x);
    gemm1_kernel<<<NNP / 128, 256, G1_SMEM>>>();
    gemm2_kernel<<<NNP / 256, 256, G2_SMEM>>>();
    gather2_kernel<<<(NN * 16 + 255) / 256, 256>>>(b2, out);
}

// round 17
// speedup vs baseline: 1.0804x; 1.0158x over previous
#include <cuda_runtime.h>
#include <cuda_bf16.h>

#define NN   50000
#define NNP  50176              // padded to multiple of 256
#define FIN  128
#define HID  256
#define NCLS 40
#define EE   600000
#define BN_EPS 1e-5f
#define NBLK 98                 // scan blocks: 98*512 = 50176 >= NN

// ---------------- device scratch (zero-initialized, no allocs) -----------
__device__ __nv_bfloat16 g_ahi[(size_t)NNP * FIN];   // hi(BN0-folded agg1)
__device__ __nv_bfloat16 g_alo[(size_t)NNP * FIN];   // lo residual
__device__ __nv_bfloat16 g_w1t_hi[HID * FIN];        // W1^T hi  [n][k]
__device__ __nv_bfloat16 g_w1t_lo[HID * FIN];        // W1^T lo
__device__ __nv_bfloat16 g_w2t_hi[48 * HID];         // W2^T hi [n][k], n pad 48
__device__ __nv_bfloat16 g_w2t_lo[48 * HID];         // W2^T lo
__device__ __nv_bfloat16 g_h1hi[(size_t)NNP * HID];  // h1 hi
__device__ __nv_bfloat16 g_h1lo[(size_t)NNP * HID];  // h1 lo
__device__ float g_s0[FIN], g_t0[FIN];               // BN0 affine
__device__ float g_s1[HID], g_d1[HID];               // BN1 scale, b1*s1+t1
__device__ int   g_deg[NN];
__device__ int   g_rowptr[NN + 1];
__device__ int   g_rank[EE];                         // edge rank within dst bucket
__device__ int   g_csr[EE];
__device__ int   g_bsum[NBLK];
__device__ float g_y[NN * NCLS];
__device__ int   g_idx64;

// ---------------- mma.sync / ldmatrix helpers (base ISA) ------------------
__device__ __forceinline__ unsigned smem_u32(const void* p) {
    unsigned a;
    asm("{ .reg .u64 t; cvta.to.shared.u64 t, %1; cvt.u32.u64 %0, t; }" : "=r"(a) : "l"(p));
    return a;
}
__device__ __forceinline__ void ldsm4(unsigned* r, unsigned addr) {
    asm volatile("ldmatrix.sync.aligned.m8n8.x4.shared.b16 {%0,%1,%2,%3}, [%4];"
                 : "=r"(r[0]), "=r"(r[1]), "=r"(r[2]), "=r"(r[3]) : "r"(addr));
}
__device__ __forceinline__ void mma_bf16(float* d, const unsigned* a, const unsigned* b) {
    asm volatile(
        "mma.sync.aligned.m16n8k16.row.col.f32.bf16.bf16.f32 "
        "{%0,%1,%2,%3}, {%4,%5,%6,%7}, {%8,%9}, {%0,%1,%2,%3};"
        : "+f"(d[0]), "+f"(d[1]), "+f"(d[2]), "+f"(d[3])
        : "r"(a[0]), "r"(a[1]), "r"(a[2]), "r"(a[3]), "r"(b[0]), "r"(b[1]));
}
__device__ __forceinline__ unsigned packbf2(float a, float b) {
    unsigned r;
    asm("cvt.rn.satfinite.bf16x2.f32 %0, %1, %2;" : "=r"(r) : "f"(b), "f"(a));
    return r;
}

extern __shared__ char dyn_smem[];

// ---------------- init: detect dtype + zero deg + BN affines + W splits ---
__global__ void init_kernel(const unsigned int* __restrict__ ei,
                            const float* __restrict__ bn0g, const float* __restrict__ bn0b,
                            const float* __restrict__ bn0m, const float* __restrict__ bn0v,
                            const float* __restrict__ W1, const float* __restrict__ b1,
                            const float* __restrict__ bn1g, const float* __restrict__ bn1b,
                            const float* __restrict__ bn1m, const float* __restrict__ bn1v,
                            const float* __restrict__ W2) {
    int t = blockIdx.x * blockDim.x + threadIdx.x;
    if (t < NN) g_deg[t] = 0;
    if (blockIdx.x == 0 && threadIdx.x < 32) {
        int l = threadIdx.x;
        unsigned any = 0;
        for (int k = l; k < 1024; k += 32) any |= ei[2 * k + 1];
#pragma unroll
        for (int off = 16; off > 0; off >>= 1) any |= __shfl_xor_sync(0xFFFFFFFFu, any, off);
        if (l == 0) g_idx64 = (any == 0) ? 1 : 0;
    }
    if (t < FIN) {
        float s0 = bn0g[t] * rsqrtf(bn0v[t] + BN_EPS);
        g_s0[t] = s0;
        g_t0[t] = bn0b[t] - bn0m[t] * s0;
    }
    if (t < HID) {
        float s1 = bn1g[t] * rsqrtf(bn1v[t] + BN_EPS);
        g_s1[t] = s1;
        g_d1[t] = b1[t] * s1 + (bn1b[t] - bn1m[t] * s1);
    }
    if (t < FIN * HID) {
        int k = t / HID;
        int n = t % HID;
        float w = W1[t];
        __nv_bfloat16 hi = __float2bfloat16_rn(w);
        __nv_bfloat16 lo = __float2bfloat16_rn(w - __bfloat162float(hi));
        g_w1t_hi[n * FIN + k] = hi;
        g_w1t_lo[n * FIN + k] = lo;
    }
    if (t < HID * NCLS) {
        int k = t / NCLS;
        int n = t % NCLS;
        float w = W2[t];
        __nv_bfloat16 hi = __float2bfloat16_rn(w);
        __nv_bfloat16 lo = __float2bfloat16_rn(w - __bfloat162float(hi));
        g_w2t_hi[n * HID + k] = hi;
        g_w2t_lo[n * HID + k] = lo;
    }
}

// ---------------- count: 8 edges/thread; save atomic return as rank -------
__global__ void count_kernel(const void* __restrict__ ei) {
    int t = blockIdx.x * blockDim.x + threadIdx.x;
    if (t >= EE / 8) return;
    int d[8];
    if (g_idx64) {
        const longlong2* p = (const longlong2*)((const long long*)ei + EE) + t * 4;
        longlong2 v0 = p[0], v1 = p[1], v2 = p[2], v3 = p[3];
        d[0] = (int)v0.x; d[1] = (int)v0.y; d[2] = (int)v1.x; d[3] = (int)v1.y;
        d[4] = (int)v2.x; d[5] = (int)v2.y; d[6] = (int)v3.x; d[7] = (int)v3.y;
    } else {
        const int4* p = (const int4*)((const int*)ei + EE) + t * 2;
        int4 v0 = p[0], v1 = p[1];
        d[0] = v0.x; d[1] = v0.y; d[2] = v0.z; d[3] = v0.w;
        d[4] = v1.x; d[5] = v1.y; d[6] = v1.z; d[7] = v1.w;
    }
    int r[8];
#pragma unroll
    for (int i = 0; i < 8; i++) r[i] = atomicAdd(&g_deg[d[i]], 1);
    int4* rb = (int4*)(g_rank + t * 8);
    rb[0] = make_int4(r[0], r[1], r[2], r[3]);
    rb[1] = make_int4(r[4], r[5], r[6], r[7]);
}

// ---------------- scan1: per-block (512) reduce of deg -> g_bsum ----------
__global__ void __launch_bounds__(512, 2) scan1_kernel() {
    __shared__ int ws[16];
    const int lane = threadIdx.x & 31;
    const int wd = threadIdx.x >> 5;
    int i = blockIdx.x * 512 + threadIdx.x;
    int v = (i < NN) ? g_deg[i] : 0;
#pragma unroll
    for (int off = 16; off > 0; off >>= 1) v += __shfl_xor_sync(0xFFFFFFFFu, v, off);
    if (lane == 0) ws[wd] = v;
    __syncthreads();
    if (wd == 0 && lane < 16) {
        int u = ws[lane];
#pragma unroll
        for (int off = 8; off > 0; off >>= 1) u += __shfl_xor_sync(0xFFFFu, u, off);
        if (lane == 0) g_bsum[blockIdx.x] = u;
    }
}

// ---------------- scan2: block offset (redundant) + shfl block scan -------
__global__ void __launch_bounds__(512, 2) scan2_kernel() {
    __shared__ int ws[16];
    __shared__ int sboff;
    const int b = blockIdx.x;
    const int t = threadIdx.x;
    const int lane = t & 31;
    const int wd = t >> 5;

    if (wd == 0) {
        int acc = 0;
#pragma unroll
        for (int base = 0; base < NBLK; base += 32) {
            int idx = base + lane;
            int u = (idx < NBLK && idx < b) ? g_bsum[idx] : 0;
#pragma unroll
            for (int off = 16; off > 0; off >>= 1) u += __shfl_xor_sync(0xFFFFFFFFu, u, off);
            acc += u;
        }
        if (lane == 0) sboff = acc;
    }

    int i = b * 512 + t;
    int v = (i < NN) ? g_deg[i] : 0;
    int s = v;
#pragma unroll
    for (int off = 1; off < 32; off <<= 1) {
        int u = __shfl_up_sync(0xFFFFFFFFu, s, off);
        if (lane >= off) s += u;
    }
    if (lane == 31) ws[wd] = s;
    __syncthreads();
    if (wd == 0 && lane < 16) {
        int u2 = ws[lane];
        int w2 = u2;
#pragma unroll
        for (int off = 1; off < 16; off <<= 1) {
            int uu = __shfl_up_sync(0xFFFFu, w2, off);
            if (lane >= off) w2 += uu;
        }
        ws[lane] = w2 - u2;
    }
    __syncthreads();
    if (i < NN) g_rowptr[i] = sboff + ws[wd] + (s - v);
    if (i == 0) g_rowptr[NN] = EE;
}

// ---------------- fill: atomic-free, pos = rowptr[dst] + rank -------------
__global__ void fill_kernel(const void* __restrict__ ei) {
    int t = blockIdx.x * blockDim.x + threadIdx.x;
    if (t >= EE / 4) return;
    int s[4], d[4];
    if (g_idx64) {
        const longlong2* sp = (const longlong2*)ei + t * 2;
        const longlong2* dp = (const longlong2*)((const long long*)ei + EE) + t * 2;
        longlong2 s0 = sp[0], s1 = sp[1], d0 = dp[0], d1 = dp[1];
        s[0] = (int)s0.x; s[1] = (int)s0.y; s[2] = (int)s1.x; s[3] = (int)s1.y;
        d[0] = (int)d0.x; d[1] = (int)d0.y; d[2] = (int)d1.x; d[3] = (int)d1.y;
    } else {
        int4 sv = ((const int4*)ei)[t];
        int4 dv = ((const int4*)((const int*)ei + EE))[t];
        s[0] = sv.x; s[1] = sv.y; s[2] = sv.z; s[3] = sv.w;
        d[0] = dv.x; d[1] = dv.y; d[2] = dv.z; d[3] = dv.w;
    }
    int4 rv = ((const int4*)g_rank)[t];
    int r[4] = {rv.x, rv.y, rv.z, rv.w};
#pragma unroll
    for (int i = 0; i < 4; i++) g_csr[__ldg(g_rowptr + d[i]) + r[i]] = s[i];
}

// ---------------- gather1: BN0-folded agg, split to bf16 hi/lo ------------
__global__ void gather1_kernel(const float* __restrict__ x) {
    int w = (blockIdx.x * blockDim.x + threadIdx.x) >> 5;   // node
    int q = threadIdx.x & 31;                               // float4 column
    if (w >= NN) return;
    const float4* xb = (const float4*)x;
    float4 acc = __ldg(xb + (size_t)w * 32 + q);
    int beg = g_rowptr[w];
    int end = g_rowptr[w + 1];
#pragma unroll 4
    for (int e = beg; e < end; e++) {
        int j = g_csr[e];
        float4 v = __ldg(xb + (size_t)j * 32 + q);
        acc.x += v.x; acc.y += v.y; acc.z += v.z; acc.w += v.w;
    }
    float cnt = 1.0f + (float)(end - beg);
    float4 s4 = *(const float4*)(g_s0 + 4 * q);
    float4 t4 = *(const float4*)(g_t0 + 4 * q);
    float a0 = acc.x * s4.x + cnt * t4.x;
    float a1 = acc.y * s4.y + cnt * t4.y;
    float a2 = acc.z * s4.z + cnt * t4.z;
    float a3 = acc.w * s4.w + cnt * t4.w;
    __nv_bfloat16 h0 = __float2bfloat16_rn(a0), h1 = __float2bfloat16_rn(a1);
    __nv_bfloat16 h2 = __float2bfloat16_rn(a2), h3 = __float2bfloat16_rn(a3);
    ushort4 hv, lv;
    hv.x = __bfloat16_as_ushort(h0); hv.y = __bfloat16_as_ushort(h1);
    hv.z = __bfloat16_as_ushort(h2); hv.w = __bfloat16_as_ushort(h3);
    lv.x = __bfloat16_as_ushort(__float2bfloat16_rn(a0 - __bfloat162float(h0)));
    lv.y = __bfloat16_as_ushort(__float2bfloat16_rn(a1 - __bfloat162float(h1)));
    lv.z = __bfloat16_as_ushort(__float2bfloat16_rn(a2 - __bfloat162float(h2)));
    lv.w = __bfloat16_as_ushort(__float2bfloat16_rn(a3 - __bfloat162float(h3)));
    size_t base = (size_t)w * FIN + 4 * q;
    *(ushort4*)(g_ahi + base) = hv;
    *(ushort4*)(g_alo + base) = lv;
}

// ---------------- GEMM1: mma.sync bf16x3, 128x256 tile per CTA ------------
// smem: Ah(32K) | Al(32K) | Bh(64K) | Bl(64K) = 192KB, XOR-swizzled rows
#define G1_SMEM 196608

__global__ void __launch_bounds__(256, 1) gemm1_kernel() {
    __shared__ float sc1[256], dc1[256];

    const int tid = threadIdx.x;
    const int wid = tid >> 5;
    const int lid = tid & 31;
    const int mBase = blockIdx.x * 128;
    const unsigned sbase = smem_u32(dyn_smem);

    sc1[tid] = g_s1[tid];
    dc1[tid] = g_d1[tid];

    // ---- load A tiles: thread t -> row t/2, chunks (t&1)*8 .. +7 ----
    {
        int row = tid >> 1;
        int half = tid & 1;
        const uint4* ah = (const uint4*)(g_ahi + (size_t)(mBase + row) * FIN);
        const uint4* al = (const uint4*)(g_alo + (size_t)(mBase + row) * FIN);
#pragma unroll
        for (int i = 0; i < 8; i++) {
            int c = half * 8 + i;
            unsigned off = row * 256 + ((unsigned)(c ^ (row & 7))) * 16;
            *(uint4*)(dyn_smem + off) = ah[c];
            *(uint4*)(dyn_smem + 32768 + off) = al[c];
        }
    }
    // ---- load B tiles: thread t -> W1^T row t, all 16 chunks ----
    {
        const uint4* bh = (const uint4*)(g_w1t_hi + (size_t)tid * FIN);
        const uint4* bl = (const uint4*)(g_w1t_lo + (size_t)tid * FIN);
#pragma unroll
        for (int c = 0; c < 16; c++) {
            unsigned off = tid * 256 + ((unsigned)(c ^ (tid & 7))) * 16;
            *(uint4*)(dyn_smem + 65536 + off) = bh[c];
            *(uint4*)(dyn_smem + 131072 + off) = bl[c];
        }
    }
    __syncthreads();

    const int wm = (wid >> 2) * 64;    // warp M offset (0 or 64)
    const int wn = (wid & 3) * 64;     // warp N offset (0,64,128,192)

    float acc[4][8][4];
#pragma unroll
    for (int mt = 0; mt < 4; mt++)
#pragma unroll
        for (int nt = 0; nt < 8; nt++)
#pragma unroll
            for (int r = 0; r < 4; r++) acc[mt][nt][r] = 0.0f;

    const int a_r = lid & 15;
    const int a_c = lid >> 4;
    const int b_r = (lid & 7) + ((lid >> 4) << 3);
    const int b_c = (lid >> 3) & 1;

#pragma unroll
    for (int pass = 0; pass < 3; pass++) {
        unsigned Ab = sbase + ((pass == 2) ? 32768u : 0u);
        unsigned Bb = sbase + 65536u + ((pass == 1) ? 65536u : 0u);
#pragma unroll
        for (int ks = 0; ks < 8; ks++) {
            unsigned a[4][4];
#pragma unroll
            for (int mt = 0; mt < 4; mt++) {
                int row = wm + mt * 16 + a_r;
                int c = ks * 2 + a_c;
                ldsm4(a[mt], Ab + row * 256 + ((unsigned)(c ^ (row & 7))) * 16);
            }
            unsigned b[8][2];
#pragma unroll
            for (int bt = 0; bt < 4; bt++) {
                int row = wn + bt * 16 + b_r;
                int c = ks * 2 + b_c;
                unsigned bb[4];
                ldsm4(bb, Bb + row * 256 + ((unsigned)(c ^ (row & 7))) * 16);
                b[bt * 2 + 0][0] = bb[0]; b[bt * 2 + 0][1] = bb[1];
                b[bt * 2 + 1][0] = bb[2]; b[bt * 2 + 1][1] = bb[3];
            }
#pragma unroll
            for (int mt = 0; mt < 4; mt++)
#pragma unroll
                for (int nt = 0; nt < 8; nt++)
                    mma_bf16(acc[mt][nt], a[mt], b[nt]);
        }
    }

    // ---- epilogue: h = max(d*s1 + (b1*s1+t1), 0), split to bf16 hi/lo ----
    const int rbase = lid >> 2;
    const int cbase = (lid & 3) * 2;
#pragma unroll
    for (int mt = 0; mt < 4; mt++) {
#pragma unroll
        for (int nt = 0; nt < 8; nt++) {
            int n0 = wn + nt * 8 + cbase;
            float s0c = sc1[n0], s1c = sc1[n0 + 1];
            float d0c = dc1[n0], d1c = dc1[n0 + 1];
            int m0 = mBase + wm + mt * 16 + rbase;
#pragma unroll
            for (int half = 0; half < 2; half++) {
                float v0 = fmaxf(acc[mt][nt][half * 2 + 0] * s0c + d0c, 0.0f);
                float v1 = fmaxf(acc[mt][nt][half * 2 + 1] * s1c + d1c, 0.0f);
                unsigned hp = packbf2(v0, v1);
                float h0f = __bfloat162float(__ushort_as_bfloat16((unsigned short)(hp & 0xFFFF)));
                float h1f = __bfloat162float(__ushort_as_bfloat16((unsigned short)(hp >> 16)));
                unsigned lp = packbf2(v0 - h0f, v1 - h1f);
                size_t idx = (size_t)(m0 + half * 8) * HID + n0;
                *(unsigned*)(g_h1hi + idx) = hp;
                *(unsigned*)(g_h1lo + idx) = lp;
            }
        }
    }
}

// ---------------- GEMM2: mma.sync bf16x3, 256x40 tile per CTA -------------
#define G2_SMEM 91648
#define G2_BH 0
#define G2_BL 25344
#define G2_AH 50688
#define G2_AL 71168

__global__ void __launch_bounds__(256, 2) gemm2_kernel() {
    const int tid = threadIdx.x;
    const int wid = tid >> 5;
    const int lid = tid & 31;
    const int mBase = blockIdx.x * 256;
    const unsigned sb = smem_u32(dyn_smem);

    for (int l = tid; l < 48 * 32; l += 256) {
        int row = l >> 5;
        int c = l & 31;
        unsigned off = row * 528 + c * 16;
        *(uint4*)(dyn_smem + G2_BH + off) = *(const uint4*)((const char*)g_w2t_hi + row * 512 + c * 16);
        *(uint4*)(dyn_smem + G2_BL + off) = *(const uint4*)((const char*)g_w2t_lo + row * 512 + c * 16);
    }

    const int a_r = lid & 15;
    const int a_c = lid >> 4;
    const int b_r = (lid & 7) + ((lid >> 4) << 3);
    const int b_c = (lid >> 3) & 1;
    const int wm = wid * 32;

    float acc[2][5][4];
#pragma unroll
    for (int mt = 0; mt < 2; mt++)
#pragma unroll
        for (int nt = 0; nt < 5; nt++)
#pragma unroll
            for (int r = 0; r < 4; r++) acc[mt][nt][r] = 0.0f;

    for (int kc = 0; kc < 8; kc++) {
        __syncthreads();
#pragma unroll
        for (int i = 0; i < 4; i++) {
            int l = tid + 256 * i;
            int row = l >> 2;
            int c = l & 3;
            unsigned off = row * 80 + c * 16;
            size_t gidx = (size_t)(mBase + row) * HID + kc * 32 + c * 8;
            *(uint4*)(dyn_smem + G2_AH + off) = *(const uint4*)(g_h1hi + gidx);
            *(uint4*)(dyn_smem + G2_AL + off) = *(const uint4*)(g_h1lo + gidx);
        }
        __syncthreads();

#pragma unroll
        for (int ks = 0; ks < 2; ks++) {
            unsigned ah[2][4], al[2][4];
#pragma unroll
            for (int mt = 0; mt < 2; mt++) {
                int row = wm + mt * 16 + a_r;
                unsigned off = row * 80 + (unsigned)(ks * 2 + a_c) * 16;
                ldsm4(ah[mt], sb + G2_AH + off);
                ldsm4(al[mt], sb + G2_AL + off);
            }
            unsigned bh[6][2], bl[6][2];
#pragma unroll
            for (int bt = 0; bt < 3; bt++) {
                int row = bt * 16 + b_r;
                unsigned off = row * 528 + (unsigned)(kc * 4 + ks * 2 + b_c) * 16;
                unsigned t0[4], t1[4];
                ldsm4(t0, sb + G2_BH + off);
                ldsm4(t1, sb + G2_BL + off);
                bh[bt * 2 + 0][0] = t0[0]; bh[bt * 2 + 0][1] = t0[1];
                bh[bt * 2 + 1][0] = t0[2]; bh[bt * 2 + 1][1] = t0[3];
                bl[bt * 2 + 0][0] = t1[0]; bl[bt * 2 + 0][1] = t1[1];
                bl[bt * 2 + 1][0] = t1[2]; bl[bt * 2 + 1][1] = t1[3];
            }
#pragma unroll
            for (int mt = 0; mt < 2; mt++)
#pragma unroll
                for (int nt = 0; nt < 5; nt++) {
                    mma_bf16(acc[mt][nt], ah[mt], bh[nt]);
                    mma_bf16(acc[mt][nt], ah[mt], bl[nt]);
                    mma_bf16(acc[mt][nt], al[mt], bh[nt]);
                }
        }
    }

    const int rbase = lid >> 2;
    const int cbase = (lid & 3) * 2;
#pragma unroll
    for (int mt = 0; mt < 2; mt++) {
#pragma unroll
        for (int nt = 0; nt < 5; nt++) {
            int n0 = nt * 8 + cbase;
            int m0 = mBase + wm + mt * 16 + rbase;
            if (m0 < NN) {
                float2 v = make_float2(acc[mt][nt][0], acc[mt][nt][1]);
                *(float2*)(g_y + m0 * NCLS + n0) = v;
            }
            if (m0 + 8 < NN) {
                float2 v = make_float2(acc[mt][nt][2], acc[mt][nt][3]);
                *(float2*)(g_y + (m0 + 8) * NCLS + n0) = v;
            }
        }
    }
}

// ---------------- gather2: out[i] = b2 + y[i] + sum y[j] ------------------
__global__ void gather2_kernel(const float* __restrict__ b2, float* __restrict__ out) {
    int h = (blockIdx.x * blockDim.x + threadIdx.x) >> 4;
    int q = threadIdx.x & 15;
    if (h >= NN || q >= 10) return;
    const float4* yb = (const float4*)g_y;
    float4 acc = __ldg((const float4*)b2 + q);
    float4 v = yb[(size_t)h * 10 + q];
    acc.x += v.x; acc.y += v.y; acc.z += v.z; acc.w += v.w;
    int beg = g_rowptr[h];
    int end = g_rowptr[h + 1];
#pragma unroll 4
    for (int e = beg; e < end; e++) {
        int j = g_csr[e];
        float4 u = __ldg(yb + (size_t)j * 10 + q);
        acc.x += u.x; acc.y += u.y; acc.z += u.z; acc.w += u.w;
    }
    ((float4*)out)[(size_t)h * 10 + q] = acc;
}

// --------------------------------------------------------------------------
extern "C" void kernel_launch(void* const* d_in, const int* in_sizes, int n_in,
                              void* d_out, int out_size) {
    const float* x    = (const float*)d_in[0];
    const void*  ei   = d_in[1];
    const float* bn0g = (const float*)d_in[2];
    const float* bn0b = (const float*)d_in[3];
    const float* bn0m = (const float*)d_in[4];
    const float* bn0v = (const float*)d_in[5];
    const float* W1   = (const float*)d_in[6];
    const float* b1   = (const float*)d_in[7];
    const float* bn1g = (const float*)d_in[8];
    const float* bn1b = (const float*)d_in[9];
    const float* bn1m = (const float*)d_in[10];
    const float* bn1v = (const float*)d_in[11];
    const float* W2   = (const float*)d_in[12];
    const float* b2   = (const float*)d_in[13];
    float* out = (float*)d_out;

    cudaFuncSetAttribute(gemm1_kernel, cudaFuncAttributeMaxDynamicSharedMemorySize,
                         G1_SMEM);
    cudaFuncSetAttribute(gemm2_kernel, cudaFuncAttributeMaxDynamicSharedMemorySize,
                         G2_SMEM);

    init_kernel<<<(NN + 255) / 256, 256>>>((const unsigned int*)ei,
                                           bn0g, bn0b, bn0m, bn0v, W1, b1,
                                           bn1g, bn1b, bn1m, bn1v, W2);
    count_kernel<<<(EE / 8 + 255) / 256, 256>>>(ei);
    scan1_kernel<<<NBLK, 512>>>();
    scan2_kernel<<<NBLK, 512>>>();
    fill_kernel<<<(EE / 4 + 255) / 256, 256>>>(ei);
    gather1_kernel<<<(NN * 32 + 255) / 256, 256>>>(x);
    gemm1_kernel<<<NNP / 128, 256, G1_SMEM>>>();
    gemm2_kernel<<<NNP / 256, 256, G2_SMEM>>>();
    gather2_kernel<<<(NN * 16 + 255) / 256, 256>>>(b2, out);
}